// round 6
// baseline (speedup 1.0000x reference)
#include <cuda_runtime.h>
#include <math.h>

// BayesRingRNN collapses exactly to a 2-scalar recurrence per batch:
// r_i(t) = u(t)*cos(phi_i) + v(t)*sin(phi_i)   (rank-2 weights, r0 in span).
//
// CTA-local producer/consumer, 2 batches per CTA (512 CTAs x 256 threads):
// warps 0-1 run the serial (u,v) chains and publish 32-step chunks into an
// 8-deep smem ring; warps 2-7 (192 threads) expand chunks to (B,T,N) with
// full store MLP. All sync is smem-local.

#define NN 80
#define TT 1500
#define CH 32
#define NCHUNK ((TT + CH - 1) / CH)   // 47 (last chunk = 28 steps)
#define NBUF 8
#define NPROD 2                        // producer warps / batches per CTA
#define CTHREADS 192                   // consumer threads per CTA

template <int LC>
__device__ __forceinline__ void expand_chunk(
    int t0, int buf, int nb, int tid2,
    const float2 (*uv)[NBUF][CH],
    const float4* __restrict__ c4, const float4* __restrict__ s4,
    float4* __restrict__ o4base)
{
    const int total = nb * LC * 20;
    #pragma unroll 4
    for (int l = tid2; l < total; l += CTHREADS) {
        const int q    = l / 20;              // const-div mul-shift
        const int n4   = l - q * 20;
        const int bl   = q / LC;              // LC literal: shift for 32
        const int step = q - bl * LC;
        const float2 z = uv[bl][buf][step];
        const float4 cc = c4[n4];
        const float4 ss = s4[n4];
        float4 o;
        o.x = fmaf(z.y, ss.x, z.x * cc.x);
        o.y = fmaf(z.y, ss.y, z.x * cc.y);
        o.z = fmaf(z.y, ss.z, z.x * cc.z);
        o.w = fmaf(z.y, ss.w, z.x * cc.w);
        __stcs(&o4base[((size_t)bl * TT + t0 + step) * 20 + n4], o);
    }
}

__global__ void __launch_bounds__(256, 8)
ring_kernel(const float* __restrict__ inputs,   // (B,T,2)
            const float* __restrict__ phi,      // (N,)
            float* __restrict__ out,            // (B,T,N) then (1,B,N)
            int B, float kz, long long out_size)
{
    __shared__ float4 c4s[NN / 4], s4s[NN / 4];
    __shared__ float2 uv_sm[NPROD][NBUF][CH];   // 4 KB ring
    __shared__ int    prod_flag[NPROD][NBUF];   // monotone chunk counters
    __shared__ int    cons_done;                // chunks fully consumed

    const int tid  = threadIdx.x;
    const int wid  = tid >> 5;
    const int lane = tid & 31;

    if (tid < NN) {
        float s, c; sincosf(phi[tid], &s, &c);
        reinterpret_cast<float*>(c4s)[tid] = c;
        reinterpret_cast<float*>(s4s)[tid] = s;
    }
    if (tid < NPROD * NBUF) reinterpret_cast<int*>(prod_flag)[tid] = 0;
    if (tid == 0) cons_done = 0;
    __syncthreads();

    const int b0 = blockIdx.x * NPROD;
    const int nb = min(NPROD, B - b0);

    if (wid < NPROD) {
        // ------------------------------------------------------- producers
        const int b = b0 + wid;
        if (b < B) {
            const float C1 = 0.01f / 3.0f;   // DT/(KP+KV)
            const float C3 = 2.0f / 3.0f;    // a_odd
            float u = 10.0f, v = 0.0f;       // r0 = 10*cos(phi)

            const float2* __restrict__ inp =
                reinterpret_cast<const float2*>(inputs) + (size_t)b * TT;
            float2 nx = inp[lane];           // prefetch chunk 0

            for (int c = 0; c < NCHUNK; ++c) {
                const int t = c * CH;
                const int chunk = (c == NCHUNK - 1) ? (TT - t) : CH;
                const int buf = c & (NBUF - 1);

                // ring backpressure
                if (c >= NBUF && lane == 0) {
                    while (*(volatile int*)&cons_done < c - NBUF + 1) __nanosleep(100);
                }
                __syncwarp();

                const float2 x = nx;
                if (t + CH + lane < TT) nx = inp[t + CH + lane];

                float kc = 0.f, ks = 0.f, gi = 0.f;
                if (lane < chunk) {
                    float s, co; sincosf(x.x, &s, &co);
                    kc = kz * co; ks = kz * s; gi = C3 * x.y;
                }
                float su = u, sv = v;
                #pragma unroll 4
                for (int j = 0; j < chunk; ++j) {
                    const float gij = __shfl_sync(0xffffffffu, gi, j);
                    const float kcj = __shfl_sync(0xffffffffu, kc, j);
                    const float ksj = __shfl_sync(0xffffffffu, ks, j);

                    const float xx = fmaf(u, u, v * v);   // |z|^2 > 0 always
                    const float y  = rsqrtf(xx);          // MUFU.RSQ
                    const float d  = fmaf(-(C1 * xx), y, 1.0f);
                    const float nu = fmaf(d, u, fmaf(-gij, v, kcj));
                    const float nv = fmaf(d, v, fmaf( gij, u, ksj));
                    u = nu; v = nv;
                    if (j == lane) { su = u; sv = v; }
                }
                if (lane < chunk) uv_sm[wid][buf][lane] = make_float2(su, sv);
                __syncwarp();
                __threadfence_block();
                if (lane == 0) *(volatile int*)&prod_flag[wid][buf] = c + 1;
            }

            // r_final (1,B,N) after the (B,T,N) block
            const long long base = (long long)B * TT * NN;
            if (out_size >= base + (long long)B * NN && lane < NN / 4) {
                const float4 cc = c4s[lane], ss = s4s[lane];
                float4 o;
                o.x = fmaf(v, ss.x, u * cc.x);
                o.y = fmaf(v, ss.y, u * cc.y);
                o.z = fmaf(v, ss.z, u * cc.z);
                o.w = fmaf(v, ss.w, u * cc.w);
                reinterpret_cast<float4*>(out + base + (size_t)b * NN)[lane] = o;
            }
        }
    } else {
        // ------------------------------------------------------- consumers
        const int tid2 = tid - NPROD * 32;
        float4* __restrict__ o4base =
            reinterpret_cast<float4*>(out) + (size_t)b0 * TT * (NN / 4);

        for (int c = 0; c < NCHUNK; ++c) {
            const int buf = c & (NBUF - 1);
            asm volatile("bar.sync 1, %0;" :: "n"(CTHREADS) : "memory"); // done w/ c-1
            if (tid2 == 0) {
                *(volatile int*)&cons_done = c;             // release ring slots
                for (int w = 0; w < nb; ++w)
                    while (*(volatile int*)&prod_flag[w][buf] < c + 1) __nanosleep(100);
            }
            asm volatile("bar.sync 1, %0;" :: "n"(CTHREADS) : "memory"); // c published

            if (c < NCHUNK - 1)
                expand_chunk<CH>(c * CH, buf, nb, tid2, uv_sm, c4s, s4s, o4base);
            else
                expand_chunk<TT - (NCHUNK - 1) * CH>(c * CH, buf, nb, tid2,
                                                     uv_sm, c4s, s4s, o4base);
        }
        asm volatile("bar.sync 1, %0;" :: "n"(CTHREADS) : "memory");
        if (tid2 == 0) *(volatile int*)&cons_done = NCHUNK;
    }
}

// --- host-side exact replica of the reference's _xi_inv (double precision) --
static double xi_f(double a, double target)
{
    const double x = (a / 2.0) * (a / 2.0);
    double t0 = 1.0, t1 = a / 2.0;
    double i0 = t0, i1 = t1;
    for (int k = 1; k < 30; ++k) {
        t0 *= x / ((double)k * (double)k);
        t1 *= x / ((double)k * (double)(k + 1));
        i0 += t0;
        i1 += t1;
    }
    return a * i1 / i0 - target;
}

static float compute_kappa_z()
{
    const double target = 15.0 * 0.01;
    double lo = 1e-3, hi = 50.0;
    for (int i = 0; i < 200; ++i) {
        const double mid = 0.5 * (lo + hi);
        if (xi_f(lo, target) * xi_f(mid, target) <= 0.0) hi = mid;
        else lo = mid;
    }
    return (float)(0.5 * (lo + hi));
}

extern "C" void kernel_launch(void* const* d_in, const int* in_sizes, int n_in,
                              void* d_out, int out_size)
{
    const float* inputs = (const float*)d_in[0];  // (B,T,2)
    const float* phi    = (const float*)d_in[4];  // (N,)
    float* out = (float*)d_out;

    const int B = in_sizes[0] / (2 * TT);
    const float kz = compute_kappa_z();

    const int blocks = (B + NPROD - 1) / NPROD;   // 2 batches per CTA -> 512
    ring_kernel<<<blocks, 256>>>(inputs, phi, out, B, kz, (long long)out_size);
}

// round 7
// speedup vs baseline: 1.1014x; 1.1014x over previous
#include <cuda_runtime.h>
#include <math.h>

// BayesRingRNN collapses exactly to a 2-scalar recurrence per batch:
// r_i(t) = u(t)*cos(phi_i) + v(t)*sin(phi_i)   (rank-2 weights, r0 in span).
//
// CTA-local producer/consumer, 4 batches per CTA, 512 threads:
//   warps 0-3  : serial (u,v) chains -> 8-deep smem ring (32-step chunks)
//   warps 4-15 : expand chunks to (B,T,N) with full store MLP
// All sync is smem-local (volatile flags + named barrier). 64-reg budget via
// __launch_bounds__(512,2) -- producers must NOT spill (R6 lesson).

#define NN 80
#define TT 1500
#define CH 32
#define NCHUNK ((TT + CH - 1) / CH)   // 47 (last chunk = 28 steps)
#define NBUF 8
#define NPROD 4                        // producer warps / batches per CTA
#define CTHREADS 384                   // consumer threads per CTA

template <int LC>
__device__ __forceinline__ void expand_chunk(
    int t0, int buf, int nb, int tid2,
    const float2 (*uv)[NBUF][CH],
    const float4* __restrict__ c4, const float4* __restrict__ s4,
    float4* __restrict__ o4base)
{
    const int total = nb * LC * 20;
    #pragma unroll 4
    for (int l = tid2; l < total; l += CTHREADS) {
        const int q    = l / 20;              // const-div mul-shift
        const int n4   = l - q * 20;
        const int bl   = q / LC;              // LC literal: shift for 32
        const int step = q - bl * LC;
        const float2 z = uv[bl][buf][step];
        const float4 cc = c4[n4];
        const float4 ss = s4[n4];
        float4 o;
        o.x = fmaf(z.y, ss.x, z.x * cc.x);
        o.y = fmaf(z.y, ss.y, z.x * cc.y);
        o.z = fmaf(z.y, ss.z, z.x * cc.z);
        o.w = fmaf(z.y, ss.w, z.x * cc.w);
        __stcs(&o4base[((size_t)bl * TT + t0 + step) * 20 + n4], o);
    }
}

__global__ void __launch_bounds__(512, 2)
ring_kernel(const float* __restrict__ inputs,   // (B,T,2)
            const float* __restrict__ phi,      // (N,)
            float* __restrict__ out,            // (B,T,N) then (1,B,N)
            int B, float kz, long long out_size)
{
    __shared__ float4 c4s[NN / 4], s4s[NN / 4];
    __shared__ float2 uv_sm[NPROD][NBUF][CH];   // 8 KB ring
    __shared__ int    prod_flag[NPROD][NBUF];   // monotone chunk counters
    __shared__ int    cons_done;                // chunks fully consumed

    const int tid  = threadIdx.x;
    const int wid  = tid >> 5;
    const int lane = tid & 31;

    if (tid < NN) {
        float s, c; sincosf(phi[tid], &s, &c);
        reinterpret_cast<float*>(c4s)[tid] = c;
        reinterpret_cast<float*>(s4s)[tid] = s;
    }
    if (tid < NPROD * NBUF) reinterpret_cast<int*>(prod_flag)[tid] = 0;
    if (tid == 0) cons_done = 0;
    __syncthreads();

    const int b0 = blockIdx.x * NPROD;
    const int nb = min(NPROD, B - b0);

    if (wid < NPROD) {
        // ------------------------------------------------------- producers
        const int b = b0 + wid;
        if (b < B) {
            const float C1 = 0.01f / 3.0f;   // DT/(KP+KV)
            const float C3 = 2.0f / 3.0f;    // a_odd
            float u = 10.0f, v = 0.0f;       // r0 = 10*cos(phi)

            const float2* __restrict__ inp =
                reinterpret_cast<const float2*>(inputs) + (size_t)b * TT;
            float2 nx = inp[lane];           // prefetch chunk 0

            for (int c = 0; c < NCHUNK; ++c) {
                const int t = c * CH;
                const int chunk = (c == NCHUNK - 1) ? (TT - t) : CH;
                const int buf = c & (NBUF - 1);

                // ring backpressure (producer runs ahead of consumer)
                if (c >= NBUF && lane == 0) {
                    while (*(volatile int*)&cons_done < c - NBUF + 1) __nanosleep(100);
                }
                __syncwarp();

                const float2 x = nx;
                if (t + CH + lane < TT) nx = inp[t + CH + lane];

                float kc = 0.f, ks = 0.f, gi = 0.f;
                if (lane < chunk) {
                    float s, co; sincosf(x.x, &s, &co);
                    kc = kz * co; ks = kz * s; gi = C3 * x.y;
                }
                float su = u, sv = v;
                #pragma unroll 4
                for (int j = 0; j < chunk; ++j) {
                    const float gij = __shfl_sync(0xffffffffu, gi, j);
                    const float kcj = __shfl_sync(0xffffffffu, kc, j);
                    const float ksj = __shfl_sync(0xffffffffu, ks, j);

                    const float xx = fmaf(u, u, v * v);   // |z|^2 > 0 always
                    const float y  = rsqrtf(xx);          // MUFU.RSQ
                    const float d  = fmaf(-(C1 * xx), y, 1.0f);
                    const float nu = fmaf(d, u, fmaf(-gij, v, kcj));
                    const float nv = fmaf(d, v, fmaf( gij, u, ksj));
                    u = nu; v = nv;
                    if (j == lane) { su = u; sv = v; }
                }
                if (lane < chunk) uv_sm[wid][buf][lane] = make_float2(su, sv);
                __syncwarp();
                __threadfence_block();
                if (lane == 0) *(volatile int*)&prod_flag[wid][buf] = c + 1;
            }

            // r_final (1,B,N) after the (B,T,N) block
            const long long base = (long long)B * TT * NN;
            if (out_size >= base + (long long)B * NN && lane < NN / 4) {
                const float4 cc = c4s[lane], ss = s4s[lane];
                float4 o;
                o.x = fmaf(v, ss.x, u * cc.x);
                o.y = fmaf(v, ss.y, u * cc.y);
                o.z = fmaf(v, ss.z, u * cc.z);
                o.w = fmaf(v, ss.w, u * cc.w);
                reinterpret_cast<float4*>(out + base + (size_t)b * NN)[lane] = o;
            }
        }
    } else {
        // ------------------------------------------------------- consumers
        const int tid2 = tid - NPROD * 32;
        float4* __restrict__ o4base =
            reinterpret_cast<float4*>(out) + (size_t)b0 * TT * (NN / 4);

        for (int c = 0; c < NCHUNK; ++c) {
            const int buf = c & (NBUF - 1);
            asm volatile("bar.sync 1, %0;" :: "n"(CTHREADS) : "memory"); // done w/ c-1
            if (tid2 == 0) {
                *(volatile int*)&cons_done = c;             // release ring slots
                for (int w = 0; w < nb; ++w)
                    while (*(volatile int*)&prod_flag[w][buf] < c + 1) __nanosleep(100);
            }
            asm volatile("bar.sync 1, %0;" :: "n"(CTHREADS) : "memory"); // c published

            if (c < NCHUNK - 1)
                expand_chunk<CH>(c * CH, buf, nb, tid2, uv_sm, c4s, s4s, o4base);
            else
                expand_chunk<TT - (NCHUNK - 1) * CH>(c * CH, buf, nb, tid2,
                                                     uv_sm, c4s, s4s, o4base);
        }
        asm volatile("bar.sync 1, %0;" :: "n"(CTHREADS) : "memory");
        if (tid2 == 0) *(volatile int*)&cons_done = NCHUNK;
    }
}

// --- host-side exact replica of the reference's _xi_inv (double precision) --
static double xi_f(double a, double target)
{
    const double x = (a / 2.0) * (a / 2.0);
    double t0 = 1.0, t1 = a / 2.0;
    double i0 = t0, i1 = t1;
    for (int k = 1; k < 30; ++k) {
        t0 *= x / ((double)k * (double)k);
        t1 *= x / ((double)k * (double)(k + 1));
        i0 += t0;
        i1 += t1;
    }
    return a * i1 / i0 - target;
}

static float compute_kappa_z()
{
    const double target = 15.0 * 0.01;
    double lo = 1e-3, hi = 50.0;
    for (int i = 0; i < 200; ++i) {
        const double mid = 0.5 * (lo + hi);
        if (xi_f(lo, target) * xi_f(mid, target) <= 0.0) hi = mid;
        else lo = mid;
    }
    return (float)(0.5 * (lo + hi));
}

extern "C" void kernel_launch(void* const* d_in, const int* in_sizes, int n_in,
                              void* d_out, int out_size)
{
    const float* inputs = (const float*)d_in[0];  // (B,T,2)
    const float* phi    = (const float*)d_in[4];  // (N,)
    float* out = (float*)d_out;

    const int B = in_sizes[0] / (2 * TT);
    const float kz = compute_kappa_z();

    const int blocks = (B + NPROD - 1) / NPROD;   // 4 batches per CTA -> 256
    ring_kernel<<<blocks, NPROD * 32 + CTHREADS>>>(inputs, phi, out, B, kz,
                                                   (long long)out_size);
}